// round 12
// baseline (speedup 1.0000x reference)
#include <cuda_runtime.h>
#include <cstdint>

// ---------------------------------------------------------------------------
// BaseGCN: kNN + Laplacian, persistent-CTA version.
//   gcn_prep : transpose x into SoA scratch g_soa[batch][{x,y,z}][4096]
//   gcn_main : 740 persistent CTAs (one wave); each CTA loops over a
//              CONTIGUOUS range of row-groups (4 rows each) -> no wave
//              transitions, point planes stay L1-resident across iterations.
// out[g,i,j] = (j==i) - (1/k) * [j in knn(i)]   (deg == k always).
//
//  zeros: 16KB smem zero buffer (init once) TMA-bulk-stored per iteration to
//         that group's 4 output rows; wait_group 0 before the group's scatter.
//  pass1: packed f32x2 distances, |x|^2 recomputed; per-thread minima tm[4]
//         -> 32 group-of-8 minima (u16 ordered prefixes)
//  thr:   warp r<4 counting-ranks the 32 minima; rank k-1 value T guarantees
//         >= k candidates <= T  =>  collected set contains the exact top-k
//  compact: thread flagged for row r iff tm[r] <= T -> flat task list (~92)
//  exec:  all 8 warps; each half-warp evaluates one task's 16 candidates
//  rank:  warps w / w+4 co-rank row (w&3) -> exact top-k (64-bit
//         (ord(dist), idx) keys => lowest-index ties, matching lax.top_k)
//  write: scatter ~k nonzeros + diagonal per row over the TMA-written zeros
// ---------------------------------------------------------------------------

constexpr int NN   = 4096;
constexpr int ROWS = 4;
constexpr int NT   = 256;
constexpr int CAP  = 64;
constexpr int MAXTASK = 1024;
constexpr int ROWBYTES = NN * 4;        // 16384
constexpr int NSM = 148;
constexpr int CTAS_PER_SM = 5;

__device__ float g_soa[4 * 3 * NN];     // 192 KB scratch (x,y,z planes)

using u64 = unsigned long long;

__device__ __forceinline__ u64 fma2(u64 a, u64 b, u64 c) {
    u64 d; asm("fma.rn.f32x2 %0, %1, %2, %3;" : "=l"(d) : "l"(a), "l"(b), "l"(c));
    return d;
}
__device__ __forceinline__ u64 mul2(u64 a, u64 b) {
    u64 d; asm("mul.rn.f32x2 %0, %1, %2;" : "=l"(d) : "l"(a), "l"(b));
    return d;
}
__device__ __forceinline__ u64 pack2(float a, float b) {
    u64 d; asm("mov.b64 %0, {%1, %2};" : "=l"(d) : "f"(a), "f"(b));
    return d;
}
__device__ __forceinline__ u64 splat2(float a) { return pack2(a, a); }
__device__ __forceinline__ float lo2(u64 v) { return __uint_as_float((unsigned)v); }
__device__ __forceinline__ float hi2(u64 v) { return __uint_as_float((unsigned)(v >> 32)); }

__device__ __forceinline__ unsigned f2ord(float f) {
    unsigned b = __float_as_uint(f);
    return b ^ ((b & 0x80000000u) ? 0xFFFFFFFFu : 0x80000000u);
}
__device__ __forceinline__ float ord2f(unsigned u) {
    unsigned b = (u & 0x80000000u) ? (u ^ 0x80000000u) : ~u;
    return __uint_as_float(b);
}
__device__ __forceinline__ unsigned smem_u32(const void* p) {
    unsigned a;
    asm("{ .reg .u64 t; cvta.to.shared.u64 t, %1; cvt.u32.u64 %0, t; }"
        : "=r"(a) : "l"(p));
    return a;
}

// ====================== prologue: AoS -> SoA ===============================
extern "C" __global__ void __launch_bounds__(NT)
gcn_prep(const float* __restrict__ x, int total) {
    int p = blockIdx.x * NT + threadIdx.x;
    if (p < total) {
        float a = x[3 * p], b = x[3 * p + 1], c = x[3 * p + 2];
        int batch = p >> 12, i = p & (NN - 1);
        float* base = g_soa + (size_t)batch * 3 * NN;
        base[i]          = a;
        base[NN + i]     = b;
        base[2 * NN + i] = c;
    }
}

// ============================== main kernel ================================
extern "C" __global__ void __launch_bounds__(NT, CTAS_PER_SM)
gcn_main(const int* __restrict__ kptr, float* __restrict__ out, int ngroups) {
    __shared__ __align__(16) float4 zbuf[ROWBYTES / 16];   // 16 KB of zeros
    __shared__ unsigned short tm16[ROWS][32];
    __shared__ u64 cand[ROWS][CAP];
    __shared__ int knn[ROWS][32];
    __shared__ unsigned short task[MAXTASK];   // (r<<8)|src_tid
    __shared__ int ntask;
    __shared__ unsigned sT16[ROWS];
    __shared__ int cnt[ROWS];
    __shared__ int act[ROWS];
    __shared__ int anyf;

    const int tid   = threadIdx.x;
    const int lane  = tid & 31;
    const int w     = tid >> 5;

    int kk = (kptr != nullptr) ? *kptr : 20;
    kk = max(1, min(kk, 32));
    const float voff = -1.0f / (float)kk;

    // ---- one-time: zero the smem TMA source buffer ----
    {
        const float4 z4 = make_float4(0.f, 0.f, 0.f, 0.f);
#pragma unroll
        for (int u = 0; u < 4; ++u) zbuf[u * NT + tid] = z4;
    }
    __syncthreads();
    if (tid == 0)
        asm volatile("fence.proxy.async.shared::cta;" ::: "memory");

    // contiguous row-group range for this CTA (batch locality across iters)
    const int g0 = (int)((long long)blockIdx.x * ngroups / gridDim.x);
    const int g1 = (int)((long long)(blockIdx.x + 1) * ngroups / gridDim.x);

    for (int grp = g0; grp < g1; ++grp) {
        const int row0  = grp * ROWS;
        const int batch = row0 >> 12;
        const int i0    = row0 & (NN - 1);
        const float* bb = g_soa + (size_t)batch * 3 * NN;
        const ulonglong2* bu = reinterpret_cast<const ulonglong2*>(bb);
        // X at bu[g], Y at bu[g+1024], Z at bu[g+2048]

        if (tid < ROWS) cnt[tid] = 0;
        if (tid == 0) {
            ntask = 0;
            // launch this group's zero-fill (overlaps with pass1 compute)
            char* ob = reinterpret_cast<char*>(out) + (size_t)row0 * ROWBYTES;
            unsigned zs = smem_u32(zbuf);
#pragma unroll
            for (int r = 0; r < ROWS; ++r) {
                asm volatile(
                    "cp.async.bulk.global.shared::cta.bulk_group [%0], [%1], %2;"
                    :: "l"(ob + r * ROWBYTES), "r"(zs), "r"(ROWBYTES)
                    : "memory");
            }
            asm volatile("cp.async.bulk.commit_group;" ::: "memory");
        }

        // ---- per-row packed constants -2*x_i ----
        u64 PMX[ROWS], PMY[ROWS], PMZ[ROWS];
#pragma unroll
        for (int r = 0; r < ROWS; ++r) {
            int i = i0 + r;
            PMX[r] = splat2(-2.0f * __ldg(&bb[i]));
            PMY[r] = splat2(-2.0f * __ldg(&bb[NN + i]));
            PMZ[r] = splat2(-2.0f * __ldg(&bb[2 * NN + i]));
        }

        // ---- pass 1: 4 candidates/iter via LDG.128; w recomputed packed ----
        float tm[ROWS];
#pragma unroll
        for (int r = 0; r < ROWS; ++r) tm[r] = 3.0e38f;
#pragma unroll 2
        for (int t = 0; t < 4; ++t) {
            int g = t * NT + tid;             // float4-group; j = 4g..4g+3
            ulonglong2 X = __ldg(&bu[g]);
            ulonglong2 Y = __ldg(&bu[g + 1024]);
            ulonglong2 Z = __ldg(&bu[g + 2048]);
            u64 W0 = fma2(X.x, X.x, fma2(Y.x, Y.x, mul2(Z.x, Z.x)));
            u64 W1 = fma2(X.y, X.y, fma2(Y.y, Y.y, mul2(Z.y, Z.y)));
#pragma unroll
            for (int r = 0; r < ROWS; ++r) {
                u64 s01 = fma2(X.x, PMX[r], fma2(Y.x, PMY[r], fma2(Z.x, PMZ[r], W0)));
                u64 s23 = fma2(X.y, PMX[r], fma2(Y.y, PMY[r], fma2(Z.y, PMZ[r], W1)));
                float m4 = fminf(fminf(lo2(s01), hi2(s01)),
                                 fminf(lo2(s23), hi2(s23)));
                tm[r] = fminf(tm[r], m4);
            }
        }
        // group-of-8 minima -> u16 ordered prefixes. Group a = tid>>3 covers
        // threads [8a,8a+8) x 4 t-iters x 4 cands = 128 disjoint candidates.
#pragma unroll
        for (int r = 0; r < ROWS; ++r) {
            float v = tm[r];
            v = fminf(v, __shfl_down_sync(0xFFFFFFFFu, v, 4, 8));
            v = fminf(v, __shfl_down_sync(0xFFFFFFFFu, v, 2, 8));
            v = fminf(v, __shfl_down_sync(0xFFFFFFFFu, v, 1, 8));
            if ((tid & 7) == 0)
                tm16[r][tid >> 3] = (unsigned short)(f2ord(v) >> 16);
        }
        __syncthreads();

        // ---- threshold: warp r<4 counting-ranks the 32 group minima ----
        unsigned T16base = 0;
        if (w < ROWS) {
            const unsigned lm = (unsigned)tm16[w][lane];
            int c = 0;
#pragma unroll
            for (int s = 0; s < 32; ++s) {
                unsigned v = __shfl_sync(0xFFFFFFFFu, lm, s);
                c += (v < lm || (v == lm && s < lane)) ? 1 : 0;
            }
            unsigned eq = __ballot_sync(0xFFFFFFFFu, c == kk - 1);
            T16base = __shfl_sync(0xFFFFFFFFu, lm, __ffs(eq) - 1);
            if (lane == 0) sT16[w] = T16base;
            knn[w][lane] = -1;                // init for rank phase
        }
        __syncthreads();

        // ---- compaction: flag owner threads (tm[r] <= T), flat task list ----
        float thrf[ROWS];
#pragma unroll
        for (int r = 0; r < ROWS; ++r)
            thrf[r] = ord2f((sT16[r] << 16) | 0xFFFFu);
#pragma unroll
        for (int r = 0; r < ROWS; ++r) {
            bool f = (tm[r] <= thrf[r]);
            unsigned m = __ballot_sync(0xFFFFFFFFu, f);
            if (m) {
                int base = 0;
                if (lane == 0) base = atomicAdd(&ntask, __popc(m));
                base = __shfl_sync(0xFFFFFFFFu, base, 0);
                if (f) {
                    int pos = base + __popc(m & ((1u << lane) - 1u));
                    if (pos < MAXTASK)
                        task[pos] = (unsigned short)((r << 8) | tid);
                }
            }
        }
        __syncthreads();

        const float th0 = thrf[0], th1 = thrf[1], th2 = thrf[2], th3 = thrf[3];

        // ---- exec: each half-warp takes one task; 16 lanes = 16 cands ----
        {
            const int ntv = min(ntask, MAXTASK);
            const int half = lane >> 4;           // 0 or 1
            const int c16  = lane & 15;           // candidate within task
            for (int tt = 2 * w; tt < ntv; tt += 16) {
                int myt = tt + half;
                if (myt < ntv) {
                    int enc = task[myt];
                    int r   = enc >> 8;
                    int src = enc & 255;
                    int j   = ((c16 >> 2) * NT + src) * 4 + (c16 & 3);
                    float xv = __ldg(&bb[j]);
                    float yv = __ldg(&bb[NN + j]);
                    float zv = __ldg(&bb[2 * NN + j]);
                    float wv = fmaf(xv, xv, fmaf(yv, yv, zv * zv));
                    u64 pmx = (r == 0) ? PMX[0] : (r == 1) ? PMX[1]
                            : (r == 2) ? PMX[2] : PMX[3];
                    u64 pmy = (r == 0) ? PMY[0] : (r == 1) ? PMY[1]
                            : (r == 2) ? PMY[2] : PMY[3];
                    u64 pmz = (r == 0) ? PMZ[0] : (r == 1) ? PMZ[1]
                            : (r == 2) ? PMZ[2] : PMZ[3];
                    float thr = (r == 0) ? th0 : (r == 1) ? th1
                              : (r == 2) ? th2 : th3;
                    float s = fmaf(xv, lo2(pmx),
                              fmaf(yv, lo2(pmy), fmaf(zv, lo2(pmz), wv)));
                    if (s <= thr) {
                        int pos = atomicAdd(&cnt[r], 1);
                        if (pos < CAP)
                            cand[r][pos] = ((u64)f2ord(s) << 32) | (unsigned)j;
                    }
                }
            }
        }
        __syncthreads();

        // ---- overflow retry (statistically unreachable; task list remains a
        //      valid cover for any lower threshold: tm <= s_hit <= T' < T) ----
        bool ovf = (cnt[0] > CAP) | (cnt[1] > CAP) | (cnt[2] > CAP)
                 | (cnt[3] > CAP) | (ntask > MAXTASK);
        if (__builtin_expect(ovf, 0)) {
            if (tid < ROWS) act[tid] = (cnt[tid] > CAP) ? 1 : 0;
            __syncthreads();
            for (int attempt = 1; attempt < 3; ++attempt) {
                if (w < ROWS && lane == 0 && act[w]) {
                    unsigned d = (unsigned)attempt;
                    sT16[w] = (T16base > d) ? (T16base - d) : 0u;
                    cnt[w] = 0;
                }
                __syncthreads();
                const int ntv = min(ntask, MAXTASK);
                const int half = lane >> 4;
                const int c16  = lane & 15;
                for (int tt = 2 * w; tt < ntv; tt += 16) {
                    int myt = tt + half;
                    if (myt < ntv) {
                        int enc = task[myt];
                        int r   = enc >> 8;
                        if (act[r]) {
                            int src = enc & 255;
                            int j   = ((c16 >> 2) * NT + src) * 4 + (c16 & 3);
                            float xv = __ldg(&bb[j]);
                            float yv = __ldg(&bb[NN + j]);
                            float zv = __ldg(&bb[2 * NN + j]);
                            float wv = fmaf(xv, xv, fmaf(yv, yv, zv * zv));
                            u64 pmx = (r == 0) ? PMX[0] : (r == 1) ? PMX[1]
                                    : (r == 2) ? PMX[2] : PMX[3];
                            u64 pmy = (r == 0) ? PMY[0] : (r == 1) ? PMY[1]
                                    : (r == 2) ? PMY[2] : PMY[3];
                            u64 pmz = (r == 0) ? PMZ[0] : (r == 1) ? PMZ[1]
                                    : (r == 2) ? PMZ[2] : PMZ[3];
                            float thr = ord2f((sT16[r] << 16) | 0xFFFFu);
                            float s = fmaf(xv, lo2(pmx),
                                      fmaf(yv, lo2(pmy), fmaf(zv, lo2(pmz), wv)));
                            if (s <= thr) {
                                int pos = atomicAdd(&cnt[r], 1);
                                if (pos < CAP)
                                    cand[r][pos] =
                                        ((u64)f2ord(s) << 32) | (unsigned)j;
                            }
                        }
                    }
                }
                __syncthreads();
                if (tid < ROWS) {
                    if (act[tid]) act[tid] = (cnt[tid] > CAP) ? 1 : 0;
                }
                if (tid == 0) {
                    int a = 0;
#pragma unroll
                    for (int r = 0; r < ROWS; ++r) a |= act[r];
                    anyf = a;
                }
                __syncthreads();
                if (!anyf) break;
            }
        }

        // ---- rank: warps w and w+4 co-rank row (w & 3); one key per lane ----
        {
            const int r = w & 3;
            const int c = min(cnt[r], CAP);
            const int slot = lane + ((w >> 2) << 5);
            u64 my = (slot < c) ? cand[r][slot] : ~0ull;
            int rk = 0;
#pragma unroll 4
            for (int s = 0; s < c; ++s)
                rk += (cand[r][s] < my) ? 1 : 0;   // LDS broadcast
            if (my != ~0ull && rk < kk)
                knn[r][rk] = (int)(unsigned)my;
        }
        // this group's TMA zero stores must land before its scatter
        if (tid == 0)
            asm volatile("cp.async.bulk.wait_group 0;" ::: "memory");
        __syncthreads();

        // ---- scatter: warp r<4 writes its row's nonzeros + diagonal ----
        if (w < ROWS) {
            const int r = w;
            const int grow = row0 + r;
            const int iloc = i0 + r;
            float* orf = out + (size_t)grow * NN;
            int j = (lane < kk) ? knn[r][lane] : -1;
            bool selfin = (j == iloc);
            unsigned fmask = __ballot_sync(0xFFFFFFFFu, selfin);
            if (lane < kk && j >= 0)
                orf[j] = selfin ? (1.0f + voff) : voff;
            if (lane == 0 && fmask == 0u)
                orf[iloc] = 1.0f;
        }
        __syncthreads();   // protect smem reuse (cnt/ntask/knn) next iter
    }
}

// ================================ launch ===================================
extern "C" void kernel_launch(void* const* d_in, const int* in_sizes, int n_in,
                              void* d_out, int out_size) {
    const float* x   = (const float*)d_in[0];
    const int*   kpt = (n_in >= 2) ? (const int*)d_in[1] : nullptr;
    float*       out = (float*)d_out;

    int total_pts = in_sizes[0] / 3;       // 16384
    int gridP = (total_pts + NT - 1) / NT; // 64
    int ngroups = total_pts / ROWS;        // 4096
    int gridM = NSM * CTAS_PER_SM;         // 740 (one wave)
    if (gridM > ngroups) gridM = ngroups;

    gcn_prep<<<gridP, NT>>>(x, total_pts);
    gcn_main<<<gridM, NT>>>(kpt, out, ngroups);
}

// round 14
// speedup vs baseline: 1.2494x; 1.2494x over previous
#include <cuda_runtime.h>
#include <cstdint>

// ---------------------------------------------------------------------------
// BaseGCN: kNN + Laplacian, two kernels (R11 structure, 6 CTAs/SM).
//   gcn_prep : transpose x into SoA scratch g_soa[batch][{x,y,z}][4096]
//   gcn_main : one CTA = 4 rows; candidate data via LDG.128 (L1/L2-resident).
// out[g,i,j] = (j==i) - (1/k) * [j in knn(i)]   (deg == k always).
//
//  zeros: 8KB smem zero buffer TMA-bulk-stored (2 x 8KB per row) to the CTA's
//         4 output rows; wait_group 0 + barrier orders the final scatter.
//  pass1: packed f32x2 distances, |x|^2 recomputed; per-thread minima tm[4]
//         -> 32 group-of-8 minima (u16 ordered prefixes)
//  thr:   warp r<4 counting-ranks the 32 minima; rank k-1 value T guarantees
//         >= k candidates <= T  =>  collected set contains the exact top-k
//  compact: thread flagged for row r iff tm[r] <= T (owner of any hit is
//         always flagged: tm <= s_hit <= T) -> flat task list (~92 entries)
//  exec:  all 8 warps; each half-warp evaluates one task's 16 candidates
//  rank:  warps w / w+4 co-rank row (w&3) -> exact top-k (64-bit
//         (ord(dist), idx) keys => lowest-index ties, matching lax.top_k)
//  write: scatter ~k nonzeros + diagonal per row over the TMA-written zeros
// ---------------------------------------------------------------------------

constexpr int NN   = 4096;
constexpr int ROWS = 4;
constexpr int NT   = 256;
constexpr int CAP  = 64;
constexpr int MAXTASK = 1024;
constexpr int ROWBYTES = NN * 4;        // 16384
constexpr int ZBYTES   = ROWBYTES / 2;  // 8192 smem zero buffer

__device__ float g_soa[4 * 3 * NN];     // 192 KB scratch (x,y,z planes)

using u64 = unsigned long long;

__device__ __forceinline__ u64 fma2(u64 a, u64 b, u64 c) {
    u64 d; asm("fma.rn.f32x2 %0, %1, %2, %3;" : "=l"(d) : "l"(a), "l"(b), "l"(c));
    return d;
}
__device__ __forceinline__ u64 mul2(u64 a, u64 b) {
    u64 d; asm("mul.rn.f32x2 %0, %1, %2;" : "=l"(d) : "l"(a), "l"(b));
    return d;
}
__device__ __forceinline__ u64 pack2(float a, float b) {
    u64 d; asm("mov.b64 %0, {%1, %2};" : "=l"(d) : "f"(a), "f"(b));
    return d;
}
__device__ __forceinline__ u64 splat2(float a) { return pack2(a, a); }
__device__ __forceinline__ float lo2(u64 v) { return __uint_as_float((unsigned)v); }
__device__ __forceinline__ float hi2(u64 v) { return __uint_as_float((unsigned)(v >> 32)); }

__device__ __forceinline__ unsigned f2ord(float f) {
    unsigned b = __float_as_uint(f);
    return b ^ ((b & 0x80000000u) ? 0xFFFFFFFFu : 0x80000000u);
}
__device__ __forceinline__ float ord2f(unsigned u) {
    unsigned b = (u & 0x80000000u) ? (u ^ 0x80000000u) : ~u;
    return __uint_as_float(b);
}
__device__ __forceinline__ unsigned smem_u32(const void* p) {
    unsigned a;
    asm("{ .reg .u64 t; cvta.to.shared.u64 t, %1; cvt.u32.u64 %0, t; }"
        : "=r"(a) : "l"(p));
    return a;
}

// ====================== prologue: AoS -> SoA ===============================
extern "C" __global__ void __launch_bounds__(NT)
gcn_prep(const float* __restrict__ x, int total) {
    int p = blockIdx.x * NT + threadIdx.x;
    if (p < total) {
        float a = x[3 * p], b = x[3 * p + 1], c = x[3 * p + 2];
        int batch = p >> 12, i = p & (NN - 1);
        float* base = g_soa + (size_t)batch * 3 * NN;
        base[i]          = a;
        base[NN + i]     = b;
        base[2 * NN + i] = c;
    }
}

// ============================== main kernel ================================
extern "C" __global__ void __launch_bounds__(NT, 6)
gcn_main(const int* __restrict__ kptr, float* __restrict__ out) {
    __shared__ __align__(16) float4 zbuf[ZBYTES / 16];   // 8 KB of zeros
    __shared__ unsigned short tm16[ROWS][32];
    __shared__ u64 cand[ROWS][CAP];
    __shared__ int knn[ROWS][32];
    __shared__ unsigned short task[MAXTASK];   // (r<<8)|src_tid
    __shared__ int ntask;
    __shared__ unsigned sT16[ROWS];
    __shared__ int cnt[ROWS];
    __shared__ int act[ROWS];
    __shared__ int anyf;

    const int tid   = threadIdx.x;
    const int lane  = tid & 31;
    const int w     = tid >> 5;
    const int row0  = blockIdx.x * ROWS;
    const int batch = row0 >> 12;
    const int i0    = row0 & (NN - 1);

    int kk = (kptr != nullptr) ? *kptr : 20;
    kk = max(1, min(kk, 32));
    const float voff = -1.0f / (float)kk;

    const float* bb = g_soa + (size_t)batch * 3 * NN;
    const ulonglong2* bu = reinterpret_cast<const ulonglong2*>(bb);
    // X at bu[g], Y at bu[g+1024], Z at bu[g+2048]

    // ---- zero smem buffer, then TMA-bulk-store zeros to the 4 rows ----
    {
        const float4 z4 = make_float4(0.f, 0.f, 0.f, 0.f);
#pragma unroll
        for (int u = 0; u < 2; ++u) zbuf[u * NT + tid] = z4;
    }
    if (tid < ROWS) cnt[tid] = 0;
    if (tid == 0) ntask = 0;
    __syncthreads();
    if (tid == 0) {
        asm volatile("fence.proxy.async.shared::cta;" ::: "memory");
        unsigned zs = smem_u32(zbuf);
        char* ob = reinterpret_cast<char*>(out) + (size_t)row0 * ROWBYTES;
#pragma unroll
        for (int h = 0; h < 2 * ROWS; ++h) {
            asm volatile(
                "cp.async.bulk.global.shared::cta.bulk_group [%0], [%1], %2;"
                :: "l"(ob + h * ZBYTES), "r"(zs), "r"(ZBYTES)
                : "memory");
        }
        asm volatile("cp.async.bulk.commit_group;" ::: "memory");
    }

    // ---- per-row packed constants -2*x_i ----
    u64 PMX[ROWS], PMY[ROWS], PMZ[ROWS];
#pragma unroll
    for (int r = 0; r < ROWS; ++r) {
        int i = i0 + r;
        PMX[r] = splat2(-2.0f * __ldg(&bb[i]));
        PMY[r] = splat2(-2.0f * __ldg(&bb[NN + i]));
        PMZ[r] = splat2(-2.0f * __ldg(&bb[2 * NN + i]));
    }

    // ---- pass 1: 4 candidates/iter via LDG.128; w recomputed packed ----
    float tm[ROWS];
#pragma unroll
    for (int r = 0; r < ROWS; ++r) tm[r] = 3.0e38f;
#pragma unroll 2
    for (int t = 0; t < 4; ++t) {
        int g = t * NT + tid;                 // float4-group; j = 4g..4g+3
        ulonglong2 X = __ldg(&bu[g]);
        ulonglong2 Y = __ldg(&bu[g + 1024]);
        ulonglong2 Z = __ldg(&bu[g + 2048]);
        u64 W0 = fma2(X.x, X.x, fma2(Y.x, Y.x, mul2(Z.x, Z.x)));
        u64 W1 = fma2(X.y, X.y, fma2(Y.y, Y.y, mul2(Z.y, Z.y)));
#pragma unroll
        for (int r = 0; r < ROWS; ++r) {
            u64 s01 = fma2(X.x, PMX[r], fma2(Y.x, PMY[r], fma2(Z.x, PMZ[r], W0)));
            u64 s23 = fma2(X.y, PMX[r], fma2(Y.y, PMY[r], fma2(Z.y, PMZ[r], W1)));
            float m4 = fminf(fminf(lo2(s01), hi2(s01)),
                             fminf(lo2(s23), hi2(s23)));
            tm[r] = fminf(tm[r], m4);
        }
    }
    // group-of-8 minima -> u16 ordered prefixes. Group a = tid>>3 covers
    // threads [8a,8a+8) x 4 t-iters x 4 cands = 128 disjoint candidates.
#pragma unroll
    for (int r = 0; r < ROWS; ++r) {
        float v = tm[r];
        v = fminf(v, __shfl_down_sync(0xFFFFFFFFu, v, 4, 8));
        v = fminf(v, __shfl_down_sync(0xFFFFFFFFu, v, 2, 8));
        v = fminf(v, __shfl_down_sync(0xFFFFFFFFu, v, 1, 8));
        if ((tid & 7) == 0)
            tm16[r][tid >> 3] = (unsigned short)(f2ord(v) >> 16);
    }
    __syncthreads();

    // ---- threshold: warp r<4 counting-ranks the 32 group minima ----
    unsigned T16base = 0;
    if (w < ROWS) {
        const unsigned lm = (unsigned)tm16[w][lane];
        int c = 0;
#pragma unroll
        for (int s = 0; s < 32; ++s) {
            unsigned v = __shfl_sync(0xFFFFFFFFu, lm, s);
            c += (v < lm || (v == lm && s < lane)) ? 1 : 0;
        }
        unsigned eq = __ballot_sync(0xFFFFFFFFu, c == kk - 1);
        T16base = __shfl_sync(0xFFFFFFFFu, lm, __ffs(eq) - 1);
        if (lane == 0) sT16[w] = T16base;
        knn[w][lane] = -1;                    // init for rank phase
    }
    __syncthreads();

    // ---- compaction: flag owner threads (tm[r] <= T), flat task list ----
    float thrf[ROWS];
#pragma unroll
    for (int r = 0; r < ROWS; ++r)
        thrf[r] = ord2f((sT16[r] << 16) | 0xFFFFu);
#pragma unroll
    for (int r = 0; r < ROWS; ++r) {
        bool f = (tm[r] <= thrf[r]);
        unsigned m = __ballot_sync(0xFFFFFFFFu, f);
        if (m) {
            int base = 0;
            if (lane == 0) base = atomicAdd(&ntask, __popc(m));
            base = __shfl_sync(0xFFFFFFFFu, base, 0);
            if (f) {
                int pos = base + __popc(m & ((1u << lane) - 1u));
                if (pos < MAXTASK)
                    task[pos] = (unsigned short)((r << 8) | tid);
            }
        }
    }
    __syncthreads();

    const float th0 = thrf[0], th1 = thrf[1], th2 = thrf[2], th3 = thrf[3];

    // ---- exec: each half-warp takes one task; 16 lanes = 16 candidates ----
    {
        const int ntv = min(ntask, MAXTASK);
        const int half = lane >> 4;               // 0 or 1
        const int c16  = lane & 15;               // candidate within task
        for (int tt = 2 * w; tt < ntv; tt += 16) {
            int myt = tt + half;
            if (myt < ntv) {
                int enc = task[myt];
                int r   = enc >> 8;
                int src = enc & 255;
                int j   = ((c16 >> 2) * NT + src) * 4 + (c16 & 3);
                float xv = __ldg(&bb[j]);
                float yv = __ldg(&bb[NN + j]);
                float zv = __ldg(&bb[2 * NN + j]);
                float wv = fmaf(xv, xv, fmaf(yv, yv, zv * zv));
                u64 pmx = (r == 0) ? PMX[0] : (r == 1) ? PMX[1]
                        : (r == 2) ? PMX[2] : PMX[3];
                u64 pmy = (r == 0) ? PMY[0] : (r == 1) ? PMY[1]
                        : (r == 2) ? PMY[2] : PMY[3];
                u64 pmz = (r == 0) ? PMZ[0] : (r == 1) ? PMZ[1]
                        : (r == 2) ? PMZ[2] : PMZ[3];
                float thr = (r == 0) ? th0 : (r == 1) ? th1
                          : (r == 2) ? th2 : th3;
                float s = fmaf(xv, lo2(pmx),
                          fmaf(yv, lo2(pmy), fmaf(zv, lo2(pmz), wv)));
                if (s <= thr) {
                    int pos = atomicAdd(&cnt[r], 1);
                    if (pos < CAP)
                        cand[r][pos] = ((u64)f2ord(s) << 32) | (unsigned)j;
                }
            }
        }
    }
    __syncthreads();

    // ---- overflow retry (statistically unreachable; task list remains a
    //      valid cover for any lower threshold: tm <= s_hit <= T' < T) ----
    bool ovf = (cnt[0] > CAP) | (cnt[1] > CAP) | (cnt[2] > CAP) | (cnt[3] > CAP)
             | (ntask > MAXTASK);
    if (__builtin_expect(ovf, 0)) {
        if (tid < ROWS) act[tid] = (cnt[tid] > CAP) ? 1 : 0;
        __syncthreads();
        for (int attempt = 1; attempt < 3; ++attempt) {
            if (w < ROWS && lane == 0 && act[w]) {
                unsigned d = (unsigned)attempt;
                sT16[w] = (T16base > d) ? (T16base - d) : 0u;
                cnt[w] = 0;
            }
            __syncthreads();
            const int ntv = min(ntask, MAXTASK);
            const int half = lane >> 4;
            const int c16  = lane & 15;
            for (int tt = 2 * w; tt < ntv; tt += 16) {
                int myt = tt + half;
                if (myt < ntv) {
                    int enc = task[myt];
                    int r   = enc >> 8;
                    if (act[r]) {
                        int src = enc & 255;
                        int j   = ((c16 >> 2) * NT + src) * 4 + (c16 & 3);
                        float xv = __ldg(&bb[j]);
                        float yv = __ldg(&bb[NN + j]);
                        float zv = __ldg(&bb[2 * NN + j]);
                        float wv = fmaf(xv, xv, fmaf(yv, yv, zv * zv));
                        u64 pmx = (r == 0) ? PMX[0] : (r == 1) ? PMX[1]
                                : (r == 2) ? PMX[2] : PMX[3];
                        u64 pmy = (r == 0) ? PMY[0] : (r == 1) ? PMY[1]
                                : (r == 2) ? PMY[2] : PMY[3];
                        u64 pmz = (r == 0) ? PMZ[0] : (r == 1) ? PMZ[1]
                                : (r == 2) ? PMZ[2] : PMZ[3];
                        float thr = ord2f((sT16[r] << 16) | 0xFFFFu);
                        float s = fmaf(xv, lo2(pmx),
                                  fmaf(yv, lo2(pmy), fmaf(zv, lo2(pmz), wv)));
                        if (s <= thr) {
                            int pos = atomicAdd(&cnt[r], 1);
                            if (pos < CAP)
                                cand[r][pos] =
                                    ((u64)f2ord(s) << 32) | (unsigned)j;
                        }
                    }
                }
            }
            __syncthreads();
            if (tid < ROWS) {
                if (act[tid]) act[tid] = (cnt[tid] > CAP) ? 1 : 0;
            }
            if (tid == 0) {
                int a = 0;
#pragma unroll
                for (int r = 0; r < ROWS; ++r) a |= act[r];
                anyf = a;
            }
            __syncthreads();
            if (!anyf) break;
        }
    }

    // ---- rank: warps w and w+4 co-rank row (w & 3); one key per lane ----
    {
        const int r = w & 3;
        const int c = min(cnt[r], CAP);
        const int slot = lane + ((w >> 2) << 5);   // w<4: 0..31, w>=4: 32..63
        u64 my = (slot < c) ? cand[r][slot] : ~0ull;
        int rk = 0;
#pragma unroll 4
        for (int s = 0; s < c; ++s)
            rk += (cand[r][s] < my) ? 1 : 0;       // LDS broadcast
        if (my != ~0ull && rk < kk)
            knn[r][rk] = (int)(unsigned)my;
    }
    // TMA zero stores must complete before the scatter overwrites entries
    if (tid == 0)
        asm volatile("cp.async.bulk.wait_group 0;" ::: "memory");
    __syncthreads();

    // ---- scatter: warp r<4 writes its row's nonzeros + diagonal ----
    if (w < ROWS) {
        const int r = w;
        const int grow = row0 + r;
        const int iloc = i0 + r;
        float* orf = out + (size_t)grow * NN;
        int j = (lane < kk) ? knn[r][lane] : -1;
        bool selfin = (j == iloc);
        unsigned fmask = __ballot_sync(0xFFFFFFFFu, selfin);
        if (lane < kk && j >= 0)
            orf[j] = selfin ? (1.0f + voff) : voff;
        if (lane == 0 && fmask == 0u)
            orf[iloc] = 1.0f;
    }
}

// ================================ launch ===================================
extern "C" void kernel_launch(void* const* d_in, const int* in_sizes, int n_in,
                              void* d_out, int out_size) {
    const float* x   = (const float*)d_in[0];
    const int*   kpt = (n_in >= 2) ? (const int*)d_in[1] : nullptr;
    float*       out = (float*)d_out;

    int total_pts = in_sizes[0] / 3;       // 16384
    int gridP = (total_pts + NT - 1) / NT; // 64
    int gridM = total_pts / ROWS;          // 4096

    gcn_prep<<<gridP, NT>>>(x, total_pts);
    gcn_main<<<gridM, NT>>>(kpt, out);
}

// round 15
// speedup vs baseline: 1.2913x; 1.0336x over previous
#include <cuda_runtime.h>
#include <cstdint>

// ---------------------------------------------------------------------------
// BaseGCN: kNN + Laplacian, two kernels.
//   gcn_prep : x -> SoA planes g_soa[batch][{x,y,z}][4096]  (pass1, packed)
//              and AoS g_aos[batch][i] = {x,y,z,|x|^2}      (exec, 1 LDG.128)
//   gcn_main : one CTA = 4 rows; 6 CTAs/SM.
// out[g,i,j] = (j==i) - (1/k) * [j in knn(i)]   (deg == k always).
//
//  zeros: 8KB smem zero buffer TMA-bulk-stored (2 x 8KB per row) to the CTA's
//         4 output rows; wait_group 0 + barrier orders the final scatter.
//  pass1: packed f32x2 distances, |x|^2 recomputed; per-thread minima tm[4]
//         -> 32 group-of-8 minima (u16 ordered prefixes)
//  thr:   warp r<4 counting-ranks the 32 minima; rank k-1 value T guarantees
//         >= k candidates <= T  =>  collected set contains the exact top-k
//  compact: thread flagged for row r iff tm[r] <= T (owner of any hit is
//         always flagged: tm <= s_hit <= T) -> flat task list (~92 entries)
//  exec:  all 8 warps; each half-warp evaluates one task's 16 candidates;
//         each candidate is ONE LDG.128 from g_aos (w precomputed there with
//         the bit-identical fmaf chain pass1 uses) -> 1/4 the L1 wavefronts
//  rank:  warps w / w+4 co-rank row (w&3) -> exact top-k (64-bit
//         (ord(dist), idx) keys => lowest-index ties, matching lax.top_k)
//  write: scatter ~k nonzeros + diagonal per row over the TMA-written zeros
// ---------------------------------------------------------------------------

constexpr int NN   = 4096;
constexpr int ROWS = 4;
constexpr int NT   = 256;
constexpr int CAP  = 64;
constexpr int MAXTASK = 1024;
constexpr int ROWBYTES = NN * 4;        // 16384
constexpr int ZBYTES   = ROWBYTES / 2;  // 8192 smem zero buffer

__device__ float  g_soa[4 * 3 * NN];    // 192 KB SoA planes (pass1)
__device__ float4 g_aos[4 * NN];        // 256 KB AoS {x,y,z,|x|^2} (exec)

using u64 = unsigned long long;

__device__ __forceinline__ u64 fma2(u64 a, u64 b, u64 c) {
    u64 d; asm("fma.rn.f32x2 %0, %1, %2, %3;" : "=l"(d) : "l"(a), "l"(b), "l"(c));
    return d;
}
__device__ __forceinline__ u64 mul2(u64 a, u64 b) {
    u64 d; asm("mul.rn.f32x2 %0, %1, %2;" : "=l"(d) : "l"(a), "l"(b));
    return d;
}
__device__ __forceinline__ u64 pack2(float a, float b) {
    u64 d; asm("mov.b64 %0, {%1, %2};" : "=l"(d) : "f"(a), "f"(b));
    return d;
}
__device__ __forceinline__ u64 splat2(float a) { return pack2(a, a); }
__device__ __forceinline__ float lo2(u64 v) { return __uint_as_float((unsigned)v); }
__device__ __forceinline__ float hi2(u64 v) { return __uint_as_float((unsigned)(v >> 32)); }

__device__ __forceinline__ unsigned f2ord(float f) {
    unsigned b = __float_as_uint(f);
    return b ^ ((b & 0x80000000u) ? 0xFFFFFFFFu : 0x80000000u);
}
__device__ __forceinline__ float ord2f(unsigned u) {
    unsigned b = (u & 0x80000000u) ? (u ^ 0x80000000u) : ~u;
    return __uint_as_float(b);
}
__device__ __forceinline__ unsigned smem_u32(const void* p) {
    unsigned a;
    asm("{ .reg .u64 t; cvta.to.shared.u64 t, %1; cvt.u32.u64 %0, t; }"
        : "=r"(a) : "l"(p));
    return a;
}

// ====================== prologue: AoS + SoA + |x|^2 ========================
extern "C" __global__ void __launch_bounds__(NT)
gcn_prep(const float* __restrict__ x, int total) {
    int p = blockIdx.x * NT + threadIdx.x;
    if (p < total) {
        float a = x[3 * p], b = x[3 * p + 1], c = x[3 * p + 2];
        int batch = p >> 12, i = p & (NN - 1);
        float* base = g_soa + (size_t)batch * 3 * NN;
        base[i]          = a;
        base[NN + i]     = b;
        base[2 * NN + i] = c;
        // |x|^2 with the exact fmaf chain pass1's packed W uses per-lane
        g_aos[p] = make_float4(a, b, c, fmaf(a, a, fmaf(b, b, c * c)));
    }
}

// ============================== main kernel ================================
extern "C" __global__ void __launch_bounds__(NT, 6)
gcn_main(const int* __restrict__ kptr, float* __restrict__ out) {
    __shared__ __align__(16) float4 zbuf[ZBYTES / 16];   // 8 KB of zeros
    __shared__ unsigned short tm16[ROWS][32];
    __shared__ u64 cand[ROWS][CAP];
    __shared__ int knn[ROWS][32];
    __shared__ unsigned short task[MAXTASK];   // (r<<8)|src_tid
    __shared__ int ntask;
    __shared__ unsigned sT16[ROWS];
    __shared__ int cnt[ROWS];
    __shared__ int act[ROWS];
    __shared__ int anyf;

    const int tid   = threadIdx.x;
    const int lane  = tid & 31;
    const int w     = tid >> 5;
    const int row0  = blockIdx.x * ROWS;
    const int batch = row0 >> 12;
    const int i0    = row0 & (NN - 1);

    int kk = (kptr != nullptr) ? *kptr : 20;
    kk = max(1, min(kk, 32));
    const float voff = -1.0f / (float)kk;

    const float* bb = g_soa + (size_t)batch * 3 * NN;
    const ulonglong2* bu = reinterpret_cast<const ulonglong2*>(bb);
    const float4* aos = g_aos + (size_t)batch * NN;
    // X at bu[g], Y at bu[g+1024], Z at bu[g+2048]

    // ---- zero smem buffer, then TMA-bulk-store zeros to the 4 rows ----
    {
        const float4 z4 = make_float4(0.f, 0.f, 0.f, 0.f);
#pragma unroll
        for (int u = 0; u < 2; ++u) zbuf[u * NT + tid] = z4;
    }
    if (tid < ROWS) cnt[tid] = 0;
    if (tid == 0) ntask = 0;
    __syncthreads();
    if (tid == 0) {
        asm volatile("fence.proxy.async.shared::cta;" ::: "memory");
        unsigned zs = smem_u32(zbuf);
        char* ob = reinterpret_cast<char*>(out) + (size_t)row0 * ROWBYTES;
#pragma unroll
        for (int h = 0; h < 2 * ROWS; ++h) {
            asm volatile(
                "cp.async.bulk.global.shared::cta.bulk_group [%0], [%1], %2;"
                :: "l"(ob + h * ZBYTES), "r"(zs), "r"(ZBYTES)
                : "memory");
        }
        asm volatile("cp.async.bulk.commit_group;" ::: "memory");
    }

    // ---- per-row packed constants -2*x_i ----
    u64 PMX[ROWS], PMY[ROWS], PMZ[ROWS];
#pragma unroll
    for (int r = 0; r < ROWS; ++r) {
        int i = i0 + r;
        PMX[r] = splat2(-2.0f * __ldg(&bb[i]));
        PMY[r] = splat2(-2.0f * __ldg(&bb[NN + i]));
        PMZ[r] = splat2(-2.0f * __ldg(&bb[2 * NN + i]));
    }

    // ---- pass 1: 4 candidates/iter via LDG.128; w recomputed packed ----
    float tm[ROWS];
#pragma unroll
    for (int r = 0; r < ROWS; ++r) tm[r] = 3.0e38f;
#pragma unroll 2
    for (int t = 0; t < 4; ++t) {
        int g = t * NT + tid;                 // float4-group; j = 4g..4g+3
        ulonglong2 X = __ldg(&bu[g]);
        ulonglong2 Y = __ldg(&bu[g + 1024]);
        ulonglong2 Z = __ldg(&bu[g + 2048]);
        u64 W0 = fma2(X.x, X.x, fma2(Y.x, Y.x, mul2(Z.x, Z.x)));
        u64 W1 = fma2(X.y, X.y, fma2(Y.y, Y.y, mul2(Z.y, Z.y)));
#pragma unroll
        for (int r = 0; r < ROWS; ++r) {
            u64 s01 = fma2(X.x, PMX[r], fma2(Y.x, PMY[r], fma2(Z.x, PMZ[r], W0)));
            u64 s23 = fma2(X.y, PMX[r], fma2(Y.y, PMY[r], fma2(Z.y, PMZ[r], W1)));
            float m4 = fminf(fminf(lo2(s01), hi2(s01)),
                             fminf(lo2(s23), hi2(s23)));
            tm[r] = fminf(tm[r], m4);
        }
    }
    // group-of-8 minima -> u16 ordered prefixes. Group a = tid>>3 covers
    // threads [8a,8a+8) x 4 t-iters x 4 cands = 128 disjoint candidates.
#pragma unroll
    for (int r = 0; r < ROWS; ++r) {
        float v = tm[r];
        v = fminf(v, __shfl_down_sync(0xFFFFFFFFu, v, 4, 8));
        v = fminf(v, __shfl_down_sync(0xFFFFFFFFu, v, 2, 8));
        v = fminf(v, __shfl_down_sync(0xFFFFFFFFu, v, 1, 8));
        if ((tid & 7) == 0)
            tm16[r][tid >> 3] = (unsigned short)(f2ord(v) >> 16);
    }
    __syncthreads();

    // ---- threshold: warp r<4 counting-ranks the 32 group minima ----
    unsigned T16base = 0;
    if (w < ROWS) {
        const unsigned lm = (unsigned)tm16[w][lane];
        int c = 0;
#pragma unroll
        for (int s = 0; s < 32; ++s) {
            unsigned v = __shfl_sync(0xFFFFFFFFu, lm, s);
            c += (v < lm || (v == lm && s < lane)) ? 1 : 0;
        }
        unsigned eq = __ballot_sync(0xFFFFFFFFu, c == kk - 1);
        T16base = __shfl_sync(0xFFFFFFFFu, lm, __ffs(eq) - 1);
        if (lane == 0) sT16[w] = T16base;
        knn[w][lane] = -1;                    // init for rank phase
    }
    __syncthreads();

    // ---- compaction: flag owner threads (tm[r] <= T), flat task list ----
    float thrf[ROWS];
#pragma unroll
    for (int r = 0; r < ROWS; ++r)
        thrf[r] = ord2f((sT16[r] << 16) | 0xFFFFu);
#pragma unroll
    for (int r = 0; r < ROWS; ++r) {
        bool f = (tm[r] <= thrf[r]);
        unsigned m = __ballot_sync(0xFFFFFFFFu, f);
        if (m) {
            int base = 0;
            if (lane == 0) base = atomicAdd(&ntask, __popc(m));
            base = __shfl_sync(0xFFFFFFFFu, base, 0);
            if (f) {
                int pos = base + __popc(m & ((1u << lane) - 1u));
                if (pos < MAXTASK)
                    task[pos] = (unsigned short)((r << 8) | tid);
            }
        }
    }
    __syncthreads();

    const float th0 = thrf[0], th1 = thrf[1], th2 = thrf[2], th3 = thrf[3];

    // ---- exec: each half-warp takes one task; 16 lanes = 16 candidates,
    //      ONE LDG.128 per candidate from the AoS plane ----
    {
        const int ntv = min(ntask, MAXTASK);
        const int half = lane >> 4;               // 0 or 1
        const int c16  = lane & 15;               // candidate within task
        for (int tt = 2 * w; tt < ntv; tt += 16) {
            int myt = tt + half;
            if (myt < ntv) {
                int enc = task[myt];
                int r   = enc >> 8;
                int src = enc & 255;
                int j   = ((c16 >> 2) * NT + src) * 4 + (c16 & 3);
                float4 p = __ldg(&aos[j]);
                u64 pmx = (r == 0) ? PMX[0] : (r == 1) ? PMX[1]
                        : (r == 2) ? PMX[2] : PMX[3];
                u64 pmy = (r == 0) ? PMY[0] : (r == 1) ? PMY[1]
                        : (r == 2) ? PMY[2] : PMY[3];
                u64 pmz = (r == 0) ? PMZ[0] : (r == 1) ? PMZ[1]
                        : (r == 2) ? PMZ[2] : PMZ[3];
                float thr = (r == 0) ? th0 : (r == 1) ? th1
                          : (r == 2) ? th2 : th3;
                float s = fmaf(p.x, lo2(pmx),
                          fmaf(p.y, lo2(pmy), fmaf(p.z, lo2(pmz), p.w)));
                if (s <= thr) {
                    int pos = atomicAdd(&cnt[r], 1);
                    if (pos < CAP)
                        cand[r][pos] = ((u64)f2ord(s) << 32) | (unsigned)j;
                }
            }
        }
    }
    __syncthreads();

    // ---- overflow retry (statistically unreachable; task list remains a
    //      valid cover for any lower threshold: tm <= s_hit <= T' < T) ----
    bool ovf = (cnt[0] > CAP) | (cnt[1] > CAP) | (cnt[2] > CAP) | (cnt[3] > CAP)
             | (ntask > MAXTASK);
    if (__builtin_expect(ovf, 0)) {
        if (tid < ROWS) act[tid] = (cnt[tid] > CAP) ? 1 : 0;
        __syncthreads();
        for (int attempt = 1; attempt < 3; ++attempt) {
            if (w < ROWS && lane == 0 && act[w]) {
                unsigned d = (unsigned)attempt;
                sT16[w] = (T16base > d) ? (T16base - d) : 0u;
                cnt[w] = 0;
            }
            __syncthreads();
            const int ntv = min(ntask, MAXTASK);
            const int half = lane >> 4;
            const int c16  = lane & 15;
            for (int tt = 2 * w; tt < ntv; tt += 16) {
                int myt = tt + half;
                if (myt < ntv) {
                    int enc = task[myt];
                    int r   = enc >> 8;
                    if (act[r]) {
                        int src = enc & 255;
                        int j   = ((c16 >> 2) * NT + src) * 4 + (c16 & 3);
                        float4 p = __ldg(&aos[j]);
                        u64 pmx = (r == 0) ? PMX[0] : (r == 1) ? PMX[1]
                                : (r == 2) ? PMX[2] : PMX[3];
                        u64 pmy = (r == 0) ? PMY[0] : (r == 1) ? PMY[1]
                                : (r == 2) ? PMY[2] : PMY[3];
                        u64 pmz = (r == 0) ? PMZ[0] : (r == 1) ? PMZ[1]
                                : (r == 2) ? PMZ[2] : PMZ[3];
                        float thr = ord2f((sT16[r] << 16) | 0xFFFFu);
                        float s = fmaf(p.x, lo2(pmx),
                                  fmaf(p.y, lo2(pmy), fmaf(p.z, lo2(pmz), p.w)));
                        if (s <= thr) {
                            int pos = atomicAdd(&cnt[r], 1);
                            if (pos < CAP)
                                cand[r][pos] =
                                    ((u64)f2ord(s) << 32) | (unsigned)j;
                        }
                    }
                }
            }
            __syncthreads();
            if (tid < ROWS) {
                if (act[tid]) act[tid] = (cnt[tid] > CAP) ? 1 : 0;
            }
            if (tid == 0) {
                int a = 0;
#pragma unroll
                for (int r = 0; r < ROWS; ++r) a |= act[r];
                anyf = a;
            }
            __syncthreads();
            if (!anyf) break;
        }
    }

    // ---- rank: warps w and w+4 co-rank row (w & 3); one key per lane ----
    {
        const int r = w & 3;
        const int c = min(cnt[r], CAP);
        const int slot = lane + ((w >> 2) << 5);   // w<4: 0..31, w>=4: 32..63
        u64 my = (slot < c) ? cand[r][slot] : ~0ull;
        int rk = 0;
#pragma unroll 4
        for (int s = 0; s < c; ++s)
            rk += (cand[r][s] < my) ? 1 : 0;       // LDS broadcast
        if (my != ~0ull && rk < kk)
            knn[r][rk] = (int)(unsigned)my;
    }
    // TMA zero stores must complete before the scatter overwrites entries
    if (tid == 0)
        asm volatile("cp.async.bulk.wait_group 0;" ::: "memory");
    __syncthreads();

    // ---- scatter: warp r<4 writes its row's nonzeros + diagonal ----
    if (w < ROWS) {
        const int r = w;
        const int grow = row0 + r;
        const int iloc = i0 + r;
        float* orf = out + (size_t)grow * NN;
        int j = (lane < kk) ? knn[r][lane] : -1;
        bool selfin = (j == iloc);
        unsigned fmask = __ballot_sync(0xFFFFFFFFu, selfin);
        if (lane < kk && j >= 0)
            orf[j] = selfin ? (1.0f + voff) : voff;
        if (lane == 0 && fmask == 0u)
            orf[iloc] = 1.0f;
    }
}

// ================================ launch ===================================
extern "C" void kernel_launch(void* const* d_in, const int* in_sizes, int n_in,
                              void* d_out, int out_size) {
    const float* x   = (const float*)d_in[0];
    const int*   kpt = (n_in >= 2) ? (const int*)d_in[1] : nullptr;
    float*       out = (float*)d_out;

    int total_pts = in_sizes[0] / 3;       // 16384
    int gridP = (total_pts + NT - 1) / NT; // 64
    int gridM = total_pts / ROWS;          // 4096

    gcn_prep<<<gridP, NT>>>(x, total_pts);
    gcn_main<<<gridM, NT>>>(kpt, out);
}